// round 10
// baseline (speedup 1.0000x reference)
#include <cuda_runtime.h>
#include <cuda_fp16.h>
#include <math.h>

// Problem constants (ManifoldGPRFilter: N=100000, D=64, E=1000000, L=10)
#define NMAX 100000
#define EMAX 1000000
#define DIM  64
#define EPSV 1e-8f

// ---------------- static device scratch (no runtime allocation) ----------------
__device__ __half2 g_Xh[(size_t)NMAX * (DIM / 2)];
__device__ __half2 g_H0[(size_t)NMAX * (DIM / 2)];
__device__ __half2 g_H1[(size_t)NMAX * (DIM / 2)];
__device__ int   g_off[NMAX + 1];
__device__ int   g_cur[NMAX];
__device__ int2  g_edge[EMAX];     // packed (src, float-bits of val)

// decoupled-lookback scan state (reset every replay by k_prep)
#define SCAN_B 1024
#define MAXBLK 128
__device__ volatile int g_flag[MAXBLK];   // 0 = unset, else block_aggregate + 1

// ---------------- prep: zero g_cur/flags, X -> fp16, Z = w0*X ----------------
__global__ void k_prep(const float* __restrict__ X, __half2* __restrict__ Xh,
                       float* __restrict__ Z, const float* __restrict__ w,
                       int n, int n4) {
    int i = blockIdx.x * blockDim.x + threadIdx.x;
    if (i < n) g_cur[i] = 0;
    if (i < MAXBLK) g_flag[i] = 0;
    if (i < n4) {
        float w0 = __ldg(w);
        float4 x = ((const float4*)X)[i];
        Xh[i * 2]     = __floats2half2_rn(x.x, x.y);
        Xh[i * 2 + 1] = __floats2half2_rn(x.z, x.w);
        float4 z;
        z.x = w0 * x.x; z.y = w0 * x.y; z.z = w0 * x.z; z.w = w0 * x.w;
        ((float4*)Z)[i] = z;
    }
}

// degree histogram into g_cur (4 edges per thread, vectorized reads)
__global__ void k_hist(const int* __restrict__ dst, int e) {
    int i = blockIdx.x * blockDim.x + threadIdx.x;
    int base = i * 4;
    if (base + 4 <= e) {
        int4 d = __ldg((const int4*)(dst + base));
        atomicAdd(&g_cur[d.x], 1);
        atomicAdd(&g_cur[d.y], 1);
        atomicAdd(&g_cur[d.z], 1);
        atomicAdd(&g_cur[d.w], 1);
    } else {
        for (int k = base; k < e; k++)
            atomicAdd(&g_cur[dst[k]], 1);
    }
}

// ---------------- single-kernel exclusive scan (PARALLEL decoupled lookback) ----------------
// Reads degrees from g_cur, writes offsets to g_off, leaves g_cur = running cursor.
// nb <= 98 blocks, all co-resident on 148 SMs -> spin is deadlock-free.
// Lookback is PARALLEL: thread t (< bid) spins on g_flag[t]; flag carries agg+1.
__global__ void k_scan(int n, int nb) {
    __shared__ int sh[SCAN_B];
    __shared__ int s_pre;
    int bid = blockIdx.x;
    int i = bid * SCAN_B + threadIdx.x;
    int v = (i < n) ? g_cur[i] : 0;
    sh[threadIdx.x] = v;
    if (threadIdx.x == 0) s_pre = 0;
    __syncthreads();
    for (int o = 1; o < SCAN_B; o <<= 1) {
        int t = 0;
        if (threadIdx.x >= o) t = sh[threadIdx.x - o];
        __syncthreads();
        if (threadIdx.x >= o) sh[threadIdx.x] += t;
        __syncthreads();
    }
    // publish this block's aggregate (value+1 in the flag itself)
    if (threadIdx.x == SCAN_B - 1)
        g_flag[bid] = sh[SCAN_B - 1] + 1;
    // parallel lookback: one thread per preceding block
    if (threadIdx.x < bid) {
        int f;
        do { f = g_flag[threadIdx.x]; } while (f == 0);
        atomicAdd(&s_pre, f - 1);
    }
    __syncthreads();
    int pre = s_pre;
    if (i < n) {
        int excl = pre + sh[threadIdx.x] - v;
        g_off[i] = excl;
        g_cur[i] = excl;
    }
    if (bid == nb - 1 && threadIdx.x == SCAN_B - 1)
        g_off[n] = pre + sh[SCAN_B - 1];
}

// scatter: 4 edges per thread, vectorized reads
__global__ void k_scatter(const int* __restrict__ src, const int* __restrict__ dst,
                          const float* __restrict__ val, int e) {
    int i = blockIdx.x * blockDim.x + threadIdx.x;
    int base = i * 4;
    if (base + 4 <= e) {
        int4   s = __ldg((const int4*)(src + base));
        int4   d = __ldg((const int4*)(dst + base));
        float4 vv = __ldg((const float4*)(val + base));
        int p0 = atomicAdd(&g_cur[d.x], 1);
        int p1 = atomicAdd(&g_cur[d.y], 1);
        int p2 = atomicAdd(&g_cur[d.z], 1);
        int p3 = atomicAdd(&g_cur[d.w], 1);
        g_edge[p0] = make_int2(s.x, __float_as_int(vv.x));
        g_edge[p1] = make_int2(s.y, __float_as_int(vv.y));
        g_edge[p2] = make_int2(s.z, __float_as_int(vv.z));
        g_edge[p3] = make_int2(s.w, __float_as_int(vv.w));
    } else {
        for (int k = base; k < e; k++) {
            int pos = atomicAdd(&g_cur[dst[k]], 1);
            g_edge[pos] = make_int2(src[k], __float_as_int(val[k]));
        }
    }
}

// ---------------- fused SpMM + hyperbolic renorm + Z accumulation ----------------
// EXACT R3 shape (measured best): one warp per destination row, edges in PAIRS:
//   lanes 0-15 gather edge e's 128B row; lanes 16-31 edge e+1's row.
__global__ __launch_bounds__(256)
void k_spmm_renorm(const __half2* __restrict__ Hin, __half2* __restrict__ Hout,
                   float* __restrict__ Z, const float* __restrict__ w,
                   int l, int n, int writeH) {
    int warp = (blockIdx.x * blockDim.x + threadIdx.x) >> 5;
    int lane = threadIdx.x & 31;
    if (warp >= n) return;

    int half = lane >> 4;
    int sub  = lane & 15;

    int beg = g_off[warp];
    int end = g_off[warp + 1];

    const uint2* Hrows = reinterpret_cast<const uint2*>(Hin);
    float4 acc = make_float4(0.f, 0.f, 0.f, 0.f);

    int e = beg;
    for (; e + 4 <= end; e += 4) {
        int2 ed0 = __ldg(&g_edge[e + half]);
        int2 ed1 = __ldg(&g_edge[e + 2 + half]);
        uint2 h0 = __ldg(Hrows + (size_t)ed0.x * 16 + sub);
        uint2 h1 = __ldg(Hrows + (size_t)ed1.x * 16 + sub);
        float v0 = __int_as_float(ed0.y);
        float v1 = __int_as_float(ed1.y);
        float2 a01 = __half22float2(*(const __half2*)&h0.x);
        float2 a23 = __half22float2(*(const __half2*)&h0.y);
        float2 b01 = __half22float2(*(const __half2*)&h1.x);
        float2 b23 = __half22float2(*(const __half2*)&h1.y);
        acc.x += v0 * a01.x + v1 * b01.x;
        acc.y += v0 * a01.y + v1 * b01.y;
        acc.z += v0 * a23.x + v1 * b23.x;
        acc.w += v0 * a23.y + v1 * b23.y;
    }
    if (e + 2 <= end) {
        int2 ed = __ldg(&g_edge[e + half]);
        uint2 h = __ldg(Hrows + (size_t)ed.x * 16 + sub);
        float v = __int_as_float(ed.y);
        float2 a01 = __half22float2(*(const __half2*)&h.x);
        float2 a23 = __half22float2(*(const __half2*)&h.y);
        acc.x += v * a01.x;
        acc.y += v * a01.y;
        acc.z += v * a23.x;
        acc.w += v * a23.y;
        e += 2;
    }
    if (e < end && half == 0) {
        int2 ed = __ldg(&g_edge[e]);
        uint2 h = __ldg(Hrows + (size_t)ed.x * 16 + sub);
        float v = __int_as_float(ed.y);
        float2 a01 = __half22float2(*(const __half2*)&h.x);
        float2 a23 = __half22float2(*(const __half2*)&h.y);
        acc.x += v * a01.x;
        acc.y += v * a01.y;
        acc.z += v * a23.x;
        acc.w += v * a23.y;
    }

    // merge parity halves
    acc.x += __shfl_down_sync(0xffffffffu, acc.x, 16);
    acc.y += __shfl_down_sync(0xffffffffu, acc.y, 16);
    acc.z += __shfl_down_sync(0xffffffffu, acc.z, 16);
    acc.w += __shfl_down_sync(0xffffffffu, acc.w, 16);

    float ss = acc.x * acc.x + acc.y * acc.y + acc.z * acc.z + acc.w * acc.w;
    #pragma unroll
    for (int o = 8; o; o >>= 1) ss += __shfl_xor_sync(0xffffffffu, ss, o);

    if (half == 0) {
        float nrm   = sqrtf(ss) + EPSV;
        float scale = tanhf(nrm) / nrm;
        float wl    = __ldg(w + l);

        float h0 = acc.x * scale;
        float h1 = acc.y * scale;
        float h2 = acc.z * scale;
        float h3 = acc.w * scale;

        if (writeH) {
            uint2 hv;
            __half2 p01 = __floats2half2_rn(h0, h1);
            __half2 p23 = __floats2half2_rn(h2, h3);
            hv.x = *(const unsigned*)&p01;
            hv.y = *(const unsigned*)&p23;
            reinterpret_cast<uint2*>(Hout)[(size_t)warp * 16 + sub] = hv;
        }

        float4* zp = reinterpret_cast<float4*>(Z + (size_t)warp * DIM) + sub;
        float4 z = *zp;
        z.x += wl * h0;
        z.y += wl * h1;
        z.z += wl * h2;
        z.w += wl * h3;
        *zp = z;
    }
}

// ---------------- launch ----------------
extern "C" void kernel_launch(void* const* d_in, const int* in_sizes, int n_in,
                              void* d_out, int out_size) {
    const float* X    = (const float*)d_in[0];
    const float* vals = (const float*)d_in[1];
    const float* w    = (const float*)d_in[2];
    const int*   src  = (const int*)d_in[3];
    const int*   dst  = (const int*)d_in[4];
    float* Z = (float*)d_out;

    int n = in_sizes[0] / DIM;
    int e = in_sizes[1];
    int L = in_sizes[2] - 1;

    __half2* xh; __half2* h0; __half2* h1;
    cudaGetSymbolAddress((void**)&xh, g_Xh);
    cudaGetSymbolAddress((void**)&h0, g_H0);
    cudaGetSymbolAddress((void**)&h1, g_H1);

    int n4 = n * DIM / 4;
    int nb = (n + SCAN_B - 1) / SCAN_B;
    int e4 = (e + 3) / 4;

    // ---- fixed stages ----
    k_prep<<<(n4 + 255) / 256, 256>>>(X, xh, Z, w, n, n4);
    k_hist<<<(e4 + 255) / 256, 256>>>(dst, e);
    k_scan<<<nb, SCAN_B>>>(n, nb);
    k_scatter<<<(e4 + 255) / 256, 256>>>(src, dst, vals, e);

    // ---- L propagation steps (R3 SpMM, measured ~27us/iter) ----
    int blocks = (n * 32 + 255) / 256;
    for (int l = 1; l <= L; l++) {
        const __half2* Hin = (l == 1) ? xh : ((l & 1) ? h1 : h0);
        __half2* Hout      = ((l & 1) ? h0 : h1);
        int writeH = (l < L) ? 1 : 0;
        k_spmm_renorm<<<blocks, 256>>>(Hin, Hout, Z, w, l, n, writeH);
    }
}

// round 11
// speedup vs baseline: 1.5072x; 1.5072x over previous
#include <cuda_runtime.h>
#include <cuda_fp16.h>
#include <math.h>

// Problem constants (ManifoldGPRFilter: N=100000, D=64, E=1000000, L=10)
#define NMAX 100000
#define EMAX 1000000
#define DIM  64
#define EPSV 1e-8f

// ---------------- static device scratch (no runtime allocation) ----------------
__device__ __half2 g_Xh[(size_t)NMAX * (DIM / 2)];
__device__ __half2 g_H0[(size_t)NMAX * (DIM / 2)];
__device__ __half2 g_H1[(size_t)NMAX * (DIM / 2)];
__device__ int   g_deg[NMAX];
__device__ int   g_off[NMAX + 1];
__device__ int   g_cur[NMAX];
__device__ int2  g_edge[EMAX];     // packed (src, float-bits of val)
__device__ int   g_bsum[1024];

// ---------------- prep: zero deg, X -> fp16, Z = w0 * X  (merged, saves a launch) ----------------
__global__ void k_prep(const float* __restrict__ X, __half2* __restrict__ Xh,
                       float* __restrict__ Z, const float* __restrict__ w,
                       int n, int n4) {
    int i = blockIdx.x * blockDim.x + threadIdx.x;
    if (i < n) g_deg[i] = 0;
    if (i < n4) {
        float w0 = __ldg(w);
        float4 x = ((const float4*)X)[i];
        Xh[i * 2]     = __floats2half2_rn(x.x, x.y);
        Xh[i * 2 + 1] = __floats2half2_rn(x.z, x.w);
        float4 z;
        z.x = w0 * x.x; z.y = w0 * x.y; z.z = w0 * x.z; z.w = w0 * x.w;
        ((float4*)Z)[i] = z;
    }
}

__global__ void k_hist(const int* __restrict__ dst, int e) {
    int i = blockIdx.x * blockDim.x + threadIdx.x;
    if (i < e) atomicAdd(&g_deg[dst[i]], 1);
}

#define SCAN_B 1024
__global__ void k_scan1(int n) {
    __shared__ int sh[SCAN_B];
    int i = blockIdx.x * SCAN_B + threadIdx.x;
    int v = (i < n) ? g_deg[i] : 0;
    sh[threadIdx.x] = v;
    __syncthreads();
    for (int o = 1; o < SCAN_B; o <<= 1) {
        int t = 0;
        if (threadIdx.x >= o) t = sh[threadIdx.x - o];
        __syncthreads();
        if (threadIdx.x >= o) sh[threadIdx.x] += t;
        __syncthreads();
    }
    if (i < n) g_off[i] = sh[threadIdx.x] - v;        // exclusive within block
    if (threadIdx.x == SCAN_B - 1) g_bsum[blockIdx.x] = sh[threadIdx.x];
}

// 128-thread block-level scan of the (<=98) block sums
__global__ void k_scan2(int nb, int n) {
    __shared__ int sh[128];
    int v = (threadIdx.x < nb) ? g_bsum[threadIdx.x] : 0;
    sh[threadIdx.x] = v;
    __syncthreads();
    for (int o = 1; o < 128; o <<= 1) {
        int t = 0;
        if (threadIdx.x >= o) t = sh[threadIdx.x - o];
        __syncthreads();
        if (threadIdx.x >= o) sh[threadIdx.x] += t;
        __syncthreads();
    }
    if (threadIdx.x < nb) g_bsum[threadIdx.x] = sh[threadIdx.x] - v;  // exclusive
    if (threadIdx.x == 127) g_off[n] = sh[127];                       // total = E
}

__global__ void k_scan3(int n) {
    int i = blockIdx.x * SCAN_B + threadIdx.x;
    if (i < n) {
        g_off[i] += g_bsum[blockIdx.x];
        g_cur[i] = g_off[i];
    }
}

__global__ void k_scatter(const int* __restrict__ src, const int* __restrict__ dst,
                          const float* __restrict__ val, int e) {
    int i = blockIdx.x * blockDim.x + threadIdx.x;
    if (i < e) {
        int d = dst[i];
        int pos = atomicAdd(&g_cur[d], 1);
        g_edge[pos] = make_int2(src[i], __float_as_int(val[i]));
    }
}

// ---------------- fused SpMM + hyperbolic renorm + Z accumulation ----------------
// One warp per destination row, processing edges in PAIRS:
//   lanes 0-15  gather edge e   's 128B row (uint2 = 4 halves per lane)
//   lanes 16-31 gather edge e+1 's row
// => one LDG.64 covers two edges' gathers, one LDG.64 covers both edges' (src,val).
__global__ __launch_bounds__(256)
void k_spmm_renorm(const __half2* __restrict__ Hin, __half2* __restrict__ Hout,
                   float* __restrict__ Z, const float* __restrict__ w,
                   int l, int n, int writeH) {
    int warp = (blockIdx.x * blockDim.x + threadIdx.x) >> 5;
    int lane = threadIdx.x & 31;
    if (warp >= n) return;

    int half = lane >> 4;      // parity group
    int sub  = lane & 15;      // column group: owns cols [4*sub, 4*sub+4)

    int beg = g_off[warp];
    int end = g_off[warp + 1];

    const uint2* Hrows = reinterpret_cast<const uint2*>(Hin);

    float4 acc = make_float4(0.f, 0.f, 0.f, 0.f);

    int e = beg;
    // 4 edges per iteration: two independent (edge-pair) chains in flight
    for (; e + 4 <= end; e += 4) {
        int2 ed0 = __ldg(&g_edge[e + half]);
        int2 ed1 = __ldg(&g_edge[e + 2 + half]);
        uint2 h0 = __ldg(Hrows + (size_t)ed0.x * 16 + sub);
        uint2 h1 = __ldg(Hrows + (size_t)ed1.x * 16 + sub);
        float v0 = __int_as_float(ed0.y);
        float v1 = __int_as_float(ed1.y);
        float2 a01 = __half22float2(*(const __half2*)&h0.x);
        float2 a23 = __half22float2(*(const __half2*)&h0.y);
        float2 b01 = __half22float2(*(const __half2*)&h1.x);
        float2 b23 = __half22float2(*(const __half2*)&h1.y);
        acc.x += v0 * a01.x + v1 * b01.x;
        acc.y += v0 * a01.y + v1 * b01.y;
        acc.z += v0 * a23.x + v1 * b23.x;
        acc.w += v0 * a23.y + v1 * b23.y;
    }
    // remaining pair
    if (e + 2 <= end) {
        int2 ed = __ldg(&g_edge[e + half]);
        uint2 h = __ldg(Hrows + (size_t)ed.x * 16 + sub);
        float v = __int_as_float(ed.y);
        float2 a01 = __half22float2(*(const __half2*)&h.x);
        float2 a23 = __half22float2(*(const __half2*)&h.y);
        acc.x += v * a01.x;
        acc.y += v * a01.y;
        acc.z += v * a23.x;
        acc.w += v * a23.y;
        e += 2;
    }
    // odd tail: only parity-0 lanes process
    if (e < end && half == 0) {
        int2 ed = __ldg(&g_edge[e]);
        uint2 h = __ldg(Hrows + (size_t)ed.x * 16 + sub);
        float v = __int_as_float(ed.y);
        float2 a01 = __half22float2(*(const __half2*)&h.x);
        float2 a23 = __half22float2(*(const __half2*)&h.y);
        acc.x += v * a01.x;
        acc.y += v * a01.y;
        acc.z += v * a23.x;
        acc.w += v * a23.y;
    }

    // merge parity halves: lane s += lane s+16
    acc.x += __shfl_down_sync(0xffffffffu, acc.x, 16);
    acc.y += __shfl_down_sync(0xffffffffu, acc.y, 16);
    acc.z += __shfl_down_sync(0xffffffffu, acc.z, 16);
    acc.w += __shfl_down_sync(0xffffffffu, acc.w, 16);

    // row norm: reduce within lanes 0-15 (valid there)
    float ss = acc.x * acc.x + acc.y * acc.y + acc.z * acc.z + acc.w * acc.w;
    #pragma unroll
    for (int o = 8; o; o >>= 1) ss += __shfl_xor_sync(0xffffffffu, ss, o);

    if (half == 0) {
        float nrm   = sqrtf(ss) + EPSV;
        float scale = tanhf(nrm) / nrm;
        float wl    = __ldg(w + l);

        float h0 = acc.x * scale;
        float h1 = acc.y * scale;
        float h2 = acc.z * scale;
        float h3 = acc.w * scale;

        if (writeH) {
            uint2 hv;
            __half2 p01 = __floats2half2_rn(h0, h1);
            __half2 p23 = __floats2half2_rn(h2, h3);
            hv.x = *(const unsigned*)&p01;
            hv.y = *(const unsigned*)&p23;
            reinterpret_cast<uint2*>(Hout)[(size_t)warp * 16 + sub] = hv;
        }

        float4* zp = reinterpret_cast<float4*>(Z + (size_t)warp * DIM) + sub;
        float4 z = *zp;
        z.x += wl * h0;
        z.y += wl * h1;
        z.z += wl * h2;
        z.w += wl * h3;
        *zp = z;
    }
}

// ---------------- launch ----------------
extern "C" void kernel_launch(void* const* d_in, const int* in_sizes, int n_in,
                              void* d_out, int out_size) {
    const float* X    = (const float*)d_in[0];
    const float* vals = (const float*)d_in[1];
    const float* w    = (const float*)d_in[2];
    const int*   src  = (const int*)d_in[3];
    const int*   dst  = (const int*)d_in[4];
    float* Z = (float*)d_out;

    int n = in_sizes[0] / DIM;
    int e = in_sizes[1];
    int L = in_sizes[2] - 1;

    __half2* xh; __half2* h0; __half2* h1;
    cudaGetSymbolAddress((void**)&xh, g_Xh);
    cudaGetSymbolAddress((void**)&h0, g_H0);
    cudaGetSymbolAddress((void**)&h1, g_H1);

    int n4 = n * DIM / 4;
    int nb = (n + SCAN_B - 1) / SCAN_B;

    // ---- prep: zero deg, X->fp16, Z = w0*X (merged) ----
    k_prep<<<(n4 + 255) / 256, 256>>>(X, xh, Z, w, n, n4);
    // ---- CSR build (R3 classic pipeline) ----
    k_hist<<<(e + 255) / 256, 256>>>(dst, e);
    k_scan1<<<nb, SCAN_B>>>(n);
    k_scan2<<<1, 128>>>(nb, n);
    k_scan3<<<nb, SCAN_B>>>(n);
    k_scatter<<<(e + 255) / 256, 256>>>(src, dst, vals, e);

    // ---- L propagation steps (ping-pong fp16 H buffers, fused Z) ----
    int blocks = (n * 32 + 255) / 256;
    for (int l = 1; l <= L; l++) {
        const __half2* Hin = (l == 1) ? xh : ((l & 1) ? h1 : h0);
        __half2* Hout      = ((l & 1) ? h0 : h1);
        int writeH = (l < L) ? 1 : 0;
        k_spmm_renorm<<<blocks, 256>>>(Hin, Hout, Z, w, l, n, writeH);
    }
}

// round 12
// speedup vs baseline: 1.6552x; 1.0982x over previous
#include <cuda_runtime.h>
#include <cuda_fp16.h>
#include <math.h>

// Problem constants (ManifoldGPRFilter: N=100000, D=64, E=1000000, L=10)
#define NMAX 100000
#define EMAX 1000000
#define DIM  64
#define EPSV 1e-8f

// ---------------- static device scratch (no runtime allocation) ----------------
__device__ __half2 g_Xh[(size_t)NMAX * (DIM / 2)];
__device__ __half2 g_H0[(size_t)NMAX * (DIM / 2)];
__device__ __half2 g_H1[(size_t)NMAX * (DIM / 2)];
__device__ int   g_deg[NMAX];
__device__ int   g_off[NMAX + 1];
__device__ int   g_cur[NMAX];
__device__ int2  g_edge[EMAX];     // packed (src, half2(val,val) bits)
__device__ int   g_bsum[1024];

// ---------------- prep: zero deg, X -> fp16, Z = w0 * X ----------------
__global__ void k_prep(const float* __restrict__ X, __half2* __restrict__ Xh,
                       float* __restrict__ Z, const float* __restrict__ w,
                       int n, int n4) {
    int i = blockIdx.x * blockDim.x + threadIdx.x;
    if (i < n) g_deg[i] = 0;
    if (i < n4) {
        float w0 = __ldg(w);
        float4 x = ((const float4*)X)[i];
        Xh[i * 2]     = __floats2half2_rn(x.x, x.y);
        Xh[i * 2 + 1] = __floats2half2_rn(x.z, x.w);
        float4 z;
        z.x = w0 * x.x; z.y = w0 * x.y; z.z = w0 * x.z; z.w = w0 * x.w;
        ((float4*)Z)[i] = z;
    }
}

__global__ void k_hist(const int* __restrict__ dst, int e) {
    int i = blockIdx.x * blockDim.x + threadIdx.x;
    if (i < e) atomicAdd(&g_deg[dst[i]], 1);
}

#define SCAN_B 1024
__global__ void k_scan1(int n) {
    __shared__ int sh[SCAN_B];
    int i = blockIdx.x * SCAN_B + threadIdx.x;
    int v = (i < n) ? g_deg[i] : 0;
    sh[threadIdx.x] = v;
    __syncthreads();
    for (int o = 1; o < SCAN_B; o <<= 1) {
        int t = 0;
        if (threadIdx.x >= o) t = sh[threadIdx.x - o];
        __syncthreads();
        if (threadIdx.x >= o) sh[threadIdx.x] += t;
        __syncthreads();
    }
    if (i < n) g_off[i] = sh[threadIdx.x] - v;        // exclusive within block
    if (threadIdx.x == SCAN_B - 1) g_bsum[blockIdx.x] = sh[threadIdx.x];
}

// 128-thread block-level scan of the (<=98) block sums
__global__ void k_scan2(int nb, int n) {
    __shared__ int sh[128];
    int v = (threadIdx.x < nb) ? g_bsum[threadIdx.x] : 0;
    sh[threadIdx.x] = v;
    __syncthreads();
    for (int o = 1; o < 128; o <<= 1) {
        int t = 0;
        if (threadIdx.x >= o) t = sh[threadIdx.x - o];
        __syncthreads();
        if (threadIdx.x >= o) sh[threadIdx.x] += t;
        __syncthreads();
    }
    if (threadIdx.x < nb) g_bsum[threadIdx.x] = sh[threadIdx.x] - v;  // exclusive
    if (threadIdx.x == 127) g_off[n] = sh[127];                       // total = E
}

__global__ void k_scan3(int n) {
    int i = blockIdx.x * SCAN_B + threadIdx.x;
    if (i < n) {
        g_off[i] += g_bsum[blockIdx.x];
        g_cur[i] = g_off[i];
    }
}

__global__ void k_scatter(const int* __restrict__ src, const int* __restrict__ dst,
                          const float* __restrict__ val, int e) {
    int i = blockIdx.x * blockDim.x + threadIdx.x;
    if (i < e) {
        int d = dst[i];
        int pos = atomicAdd(&g_cur[d], 1);
        __half2 v2 = __floats2half2_rn(val[i], val[i]);
        g_edge[pos] = make_int2(src[i], *(const int*)&v2);
    }
}

// ---------------- fused SpMM + hyperbolic renorm + Z accumulation ----------------
// One warp per destination row, edges in PAIRS:
//   lanes 0-15  gather edge e's 128B row; lanes 16-31 edge e+1's row.
// Accumulation in half2 via HFMA2 (no per-edge converts).
__global__ __launch_bounds__(256)
void k_spmm_renorm(const __half2* __restrict__ Hin, __half2* __restrict__ Hout,
                   float* __restrict__ Z, const float* __restrict__ w,
                   int l, int n, int writeH) {
    int warp = (blockIdx.x * blockDim.x + threadIdx.x) >> 5;
    int lane = threadIdx.x & 31;
    if (warp >= n) return;

    int half = lane >> 4;      // parity group
    int sub  = lane & 15;      // column group: owns cols [4*sub, 4*sub+4)

    int beg = g_off[warp];
    int end = g_off[warp + 1];

    const uint2* Hrows = reinterpret_cast<const uint2*>(Hin);

    __half2 a01 = __float2half2_rn(0.f);
    __half2 a23 = __float2half2_rn(0.f);

    int e = beg;
    // 4 edges per iteration: two independent edge-pair chains in flight
    for (; e + 4 <= end; e += 4) {
        int2 ed0 = __ldg(&g_edge[e + half]);
        int2 ed1 = __ldg(&g_edge[e + 2 + half]);
        uint2 h0 = __ldg(Hrows + (size_t)ed0.x * 16 + sub);
        uint2 h1 = __ldg(Hrows + (size_t)ed1.x * 16 + sub);
        __half2 v0 = *(const __half2*)&ed0.y;
        __half2 v1 = *(const __half2*)&ed1.y;
        a01 = __hfma2(v0, *(const __half2*)&h0.x, a01);
        a23 = __hfma2(v0, *(const __half2*)&h0.y, a23);
        a01 = __hfma2(v1, *(const __half2*)&h1.x, a01);
        a23 = __hfma2(v1, *(const __half2*)&h1.y, a23);
    }
    // remaining pair
    if (e + 2 <= end) {
        int2 ed = __ldg(&g_edge[e + half]);
        uint2 h = __ldg(Hrows + (size_t)ed.x * 16 + sub);
        __half2 v = *(const __half2*)&ed.y;
        a01 = __hfma2(v, *(const __half2*)&h.x, a01);
        a23 = __hfma2(v, *(const __half2*)&h.y, a23);
        e += 2;
    }
    // odd tail: only parity-0 lanes process
    if (e < end && half == 0) {
        int2 ed = __ldg(&g_edge[e]);
        uint2 h = __ldg(Hrows + (size_t)ed.x * 16 + sub);
        __half2 v = *(const __half2*)&ed.y;
        a01 = __hfma2(v, *(const __half2*)&h.x, a01);
        a23 = __hfma2(v, *(const __half2*)&h.y, a23);
    }

    // to float for reduction / renorm
    float2 f01 = __half22float2(a01);
    float2 f23 = __half22float2(a23);
    float ax = f01.x, ay = f01.y, az = f23.x, aw = f23.y;

    // merge parity halves: lane s += lane s+16
    ax += __shfl_down_sync(0xffffffffu, ax, 16);
    ay += __shfl_down_sync(0xffffffffu, ay, 16);
    az += __shfl_down_sync(0xffffffffu, az, 16);
    aw += __shfl_down_sync(0xffffffffu, aw, 16);

    // row norm: reduce within lanes 0-15
    float ss = ax * ax + ay * ay + az * az + aw * aw;
    #pragma unroll
    for (int o = 8; o; o >>= 1) ss += __shfl_xor_sync(0xffffffffu, ss, o);

    if (half == 0) {
        float nrm   = sqrtf(ss) + EPSV;
        float scale = tanhf(nrm) / nrm;
        float wl    = __ldg(w + l);

        float h0 = ax * scale;
        float h1 = ay * scale;
        float h2 = az * scale;
        float h3 = aw * scale;

        if (writeH) {
            uint2 hv;
            __half2 p01 = __floats2half2_rn(h0, h1);
            __half2 p23 = __floats2half2_rn(h2, h3);
            hv.x = *(const unsigned*)&p01;
            hv.y = *(const unsigned*)&p23;
            reinterpret_cast<uint2*>(Hout)[(size_t)warp * 16 + sub] = hv;
        }

        float4* zp = reinterpret_cast<float4*>(Z + (size_t)warp * DIM) + sub;
        float4 z = *zp;
        z.x += wl * h0;
        z.y += wl * h1;
        z.z += wl * h2;
        z.w += wl * h3;
        *zp = z;
    }
}

// ---------------- launch ----------------
extern "C" void kernel_launch(void* const* d_in, const int* in_sizes, int n_in,
                              void* d_out, int out_size) {
    const float* X    = (const float*)d_in[0];
    const float* vals = (const float*)d_in[1];
    const float* w    = (const float*)d_in[2];
    const int*   src  = (const int*)d_in[3];
    const int*   dst  = (const int*)d_in[4];
    float* Z = (float*)d_out;

    int n = in_sizes[0] / DIM;
    int e = in_sizes[1];
    int L = in_sizes[2] - 1;

    __half2* xh; __half2* h0; __half2* h1;
    cudaGetSymbolAddress((void**)&xh, g_Xh);
    cudaGetSymbolAddress((void**)&h0, g_H0);
    cudaGetSymbolAddress((void**)&h1, g_H1);

    int n4 = n * DIM / 4;
    int nb = (n + SCAN_B - 1) / SCAN_B;

    // ---- prep: zero deg, X->fp16, Z = w0*X (merged) ----
    k_prep<<<(n4 + 255) / 256, 256>>>(X, xh, Z, w, n, n4);
    // ---- CSR build ----
    k_hist<<<(e + 255) / 256, 256>>>(dst, e);
    k_scan1<<<nb, SCAN_B>>>(n);
    k_scan2<<<1, 128>>>(nb, n);
    k_scan3<<<nb, SCAN_B>>>(n);
    k_scatter<<<(e + 255) / 256, 256>>>(src, dst, vals, e);

    // ---- L propagation steps (ping-pong fp16 H buffers, fused Z) ----
    int blocks = (n * 32 + 255) / 256;
    for (int l = 1; l <= L; l++) {
        const __half2* Hin = (l == 1) ? xh : ((l & 1) ? h1 : h0);
        __half2* Hout      = ((l & 1) ? h0 : h1);
        int writeH = (l < L) ? 1 : 0;
        k_spmm_renorm<<<blocks, 256>>>(Hin, Hout, Z, w, l, n, writeH);
    }
}